// round 13
// baseline (speedup 1.0000x reference)
#include <cuda_runtime.h>
#include <cuda_fp16.h>

#define RR 8
#define BB 8
#define LL 2048
#define PP 16384
#define HQ 32
#define HKV 8
#define GG 4
#define DD 128
#define NSPLIT 16
#define CHUNK (LL / NSPLIT)   // 128
#define TILE 16
#define RS (RR * NSPLIT)      // 128 partials per (b, hq)
#define SCALE_F 0.08838834764831845f
#define NEGINF -1.0e30f
#define HD (HKV * DD)         // 1024 floats per page row

// Dynamic smem layout (float offsets):
//   [0    .. 4096)  Ks[2][TILE*DD]   (16KB)
//   [4096 .. 8192)  Vs[2][TILE*DD]   (16KB)
//   [8192 .. 8320)  pg_all (128 ints)
//   [8320 .. 8384)  s_s (TILE*4)
//   [8384 .. 8448)  p_s (TILE*4)
//   [8448 .. 8460)  sc, m_fin, l_fin
#define SM_K(s)   (smf + (s) * (TILE * DD))
#define SM_V(s)   (smf + 4096 + (s) * (TILE * DD))
#define SM_PG     ((int*)(smf + 8192))
#define SM_S      (smf + 8320)
#define SM_P      (smf + 8384)
#define SM_SC     (smf + 8448)
#define SM_MF     (smf + 8452)
#define SM_LF     (smf + 8456)
#define SMEM_BYTES (8460 * 4)

// Scratch for split-KV partials (device globals; no runtime allocation).
// g_po:   fp16 [i][bh][d] — halves the scratch round-trip (16.8 -> 8.4 MB).
// g_plse: fp32 [bh][i]    — combine reads one coalesced 512B row.
__device__ __half g_po[RS * BB * HQ * DD];
__device__ float  g_plse[BB * HQ * RS];

// Stage one 16-token tile of K and V (8KB + 8KB) via cp.async.
// 512 chunks of 16B each; 4 K-chunks + 4 V-chunks per thread.
__device__ __forceinline__ void stage_tile(float* smf, int tid, int nbase,
                                           int bufi,
                                           const float* __restrict__ kh,
                                           const float* __restrict__ vhh)
{
    const unsigned kd = (unsigned)__cvta_generic_to_shared(SM_K(bufi));
    const unsigned vd = (unsigned)__cvta_generic_to_shared(SM_V(bufi));
    #pragma unroll
    for (int i = 0; i < 4; ++i) {
        const int c   = i * 128 + tid;    // 0..511 chunk id (16B)
        const int tok = c >> 5;           // 0..15
        const int off = (c & 31) << 2;    // float offset in row
        const long prow = (long)SM_PG[nbase + tok] * HD;
        const unsigned doff = (unsigned)((tok * DD + off) << 2);
        asm volatile("cp.async.cg.shared.global [%0], [%1], 16;\n"
                     :: "r"(kd + doff), "l"(kh + prow + off));
        asm volatile("cp.async.cg.shared.global [%0], [%1], 16;\n"
                     :: "r"(vd + doff), "l"(vhh + prow + off));
    }
}

__global__ void __launch_bounds__(128)
decode_kernel(const float* __restrict__ q,
              const float* __restrict__ kc,
              const float* __restrict__ vc,
              const int* __restrict__ lens,
              const int* __restrict__ bt)
{
    extern __shared__ float smf[];

    const int split = blockIdx.x;
    const int hkv   = blockIdx.y;
    const int rb    = blockIdx.z;          // r*BB + b
    const int r     = rb >> 3;
    const int b     = rb & 7;
    const int tid   = threadIdx.x;
    const int wid   = tid >> 5;            // 0..3  (warp == head for softmax)
    const int lane  = tid & 31;
    const int half  = lane >> 4;
    const int hl    = lane & 15;           // lane within half-warp
    const int hw    = wid * 2 + half;      // half-warp id 0..7

    const int kv_len = lens[rb];
    const int start  = split * CHUNK;
    const int end    = min(start + CHUNK, kv_len);
    const int rsplit = r * NSPLIT + split;            // partial index i
    const int pbase  = (rsplit * BB + b) * HQ + hkv * GG;
    const int lbase  = (b * HQ + hkv * GG) * RS + rsplit;

    if (end <= start) {
        if (tid < GG)
            g_plse[lbase + tid * RS] = NEGINF;
        return;
    }
    const int len    = end - start;                 // 1..128
    const int ntiles = (len + TILE - 1) / TILE;     // 1..8

    // Q into registers: head g, dims hl*4..+3 (lo) and 64+hl*4..+3 (hi).
    // Quarter-warp-contiguous mapping -> conflict-free LDS.128 in Phase A.
    const float* qb = q + (b * HQ + hkv * GG) * DD + hl * 4;
    float4 q0[GG], q1[GG];
    #pragma unroll
    for (int g = 0; g < GG; ++g) {
        q0[g] = *(const float4*)(qb + g * DD);
        q1[g] = *(const float4*)(qb + g * DD + 64);
    }

    const int*   btb = bt + rb * LL + start;
    const float* kh  = kc + (long)r * PP * HD + hkv * DD;
    const float* vhh = vc + (long)r * PP * HD + hkv * DD;

    // ---- Preload all pages for this chunk (one volley, page 0 for invalid).
    SM_PG[tid] = (tid < len) ? __ldg(btb + tid) : 0;
    __syncthreads();

    // ---- Prime: stage tile 0.
    stage_tile(smf, tid, 0, 0, kh, vhh);
    asm volatile("cp.async.commit_group;\n" ::: "memory");

    float acc0 = 0.f, acc1 = 0.f, acc2 = 0.f, acc3 = 0.f;
    float m_run = NEGINF, l_run = 0.f;

    for (int n = 0; n < ntiles; ++n) {
        const int buf   = n & 1;
        const int tbase = n * TILE;
        const int nt    = min(TILE, len - tbase);

        asm volatile("cp.async.wait_group 0;\n" ::: "memory");  // tile n ready
        __syncthreads();   // all see K/V(n); all finished Phase B(n-1)

        // Stage tile n+1 AFTER the barrier: its buffer (buf^1) was read by
        // Phase B(n-1), which every thread completed before this barrier.
        if (n + 1 < ntiles) {
            stage_tile(smf, tid, tbase + TILE, buf ^ 1, kh, vhh);
            asm volatile("cp.async.commit_group;\n" ::: "memory");
        }

        // ---- Phase A: scores from smem K. Half-warp per token, 2 passes.
        const float* Kb = SM_K(buf);
        #pragma unroll
        for (int pass = 0; pass < 2; ++pass) {
            const int tt = pass * 8 + hw;                // token in tile
            const float* kr = Kb + tt * DD + hl * 4;
            const float4 k0 = *(const float4*)kr;
            const float4 k1 = *(const float4*)(kr + 64);

            float s0 = q0[0].x*k0.x + q0[0].y*k0.y + q0[0].z*k0.z + q0[0].w*k0.w
                     + q1[0].x*k1.x + q1[0].y*k1.y + q1[0].z*k1.z + q1[0].w*k1.w;
            float s1 = q0[1].x*k0.x + q0[1].y*k0.y + q0[1].z*k0.z + q0[1].w*k0.w
                     + q1[1].x*k1.x + q1[1].y*k1.y + q1[1].z*k1.z + q1[1].w*k1.w;
            float s2 = q0[2].x*k0.x + q0[2].y*k0.y + q0[2].z*k0.z + q0[2].w*k0.w
                     + q1[2].x*k1.x + q1[2].y*k1.y + q1[2].z*k1.z + q1[2].w*k1.w;
            float s3 = q0[3].x*k0.x + q0[3].y*k0.y + q0[3].z*k0.z + q0[3].w*k0.w
                     + q1[3].x*k1.x + q1[3].y*k1.y + q1[3].z*k1.z + q1[3].w*k1.w;

            #pragma unroll
            for (int off = 8; off; off >>= 1) {
                s0 += __shfl_xor_sync(0xffffffffu, s0, off);
                s1 += __shfl_xor_sync(0xffffffffu, s1, off);
                s2 += __shfl_xor_sync(0xffffffffu, s2, off);
                s3 += __shfl_xor_sync(0xffffffffu, s3, off);
            }
            if (hl == 0) {
                float4* s4 = (float4*)SM_S;
                s4[tt] = (tt < nt) ? make_float4(s0 * SCALE_F, s1 * SCALE_F,
                                                 s2 * SCALE_F, s3 * SCALE_F)
                                   : make_float4(NEGINF, NEGINF, NEGINF, NEGINF);
            }
        }
        __syncthreads();   // sync1: s_s ready

        // ---- Online softmax: warp `wid` owns head `wid`. TILE=16, so both
        //      16-lane halves hold duplicate values; half-reductions give the
        //      full, warp-uniform max and sum.
        {
            const float xa = SM_S[hl * 4 + wid];
            float x = xa;
            #pragma unroll
            for (int off = 8; off; off >>= 1)
                x = fmaxf(x, __shfl_xor_sync(0xffffffffu, x, off));
            const float mn  = fmaxf(m_run, x);
            const float scl = __expf(m_run - mn);
            m_run = mn;
            if (lane == 0) SM_SC[wid] = scl;
            const float pa = __expf(xa - mn);
            if (half == 0) SM_P[hl * 4 + wid] = pa;
            float ps = pa;
            #pragma unroll
            for (int off = 8; off; off >>= 1)
                ps += __shfl_xor_sync(0xffffffffu, ps, off);
            l_run = l_run * scl + ps;
        }
        __syncthreads();   // sync2: p_s / sc_s ready

        // ---- Rescale + Phase B: thread tid owns dim d = tid for all 4 heads.
        const float c0 = SM_SC[0], c1 = SM_SC[1], c2 = SM_SC[2], c3 = SM_SC[3];
        acc0 *= c0; acc1 *= c1; acc2 *= c2; acc3 *= c3;

        const float4* p4s = (const float4*)SM_P;
        const float*  Vb  = SM_V(buf) + tid;
        #pragma unroll 8
        for (int j = 0; j < nt; ++j) {
            const float4 p4 = p4s[j];
            const float  v  = Vb[j * DD];
            acc0 += p4.x * v; acc1 += p4.y * v;
            acc2 += p4.z * v; acc3 += p4.w * v;
        }
        // No trailing barrier: the post-wait __syncthreads at the top of the
        // next iteration orders these reads before any buffer reuse.
    }

    if (lane == 0) { SM_MF[wid] = m_run; SM_LF[wid] = l_run; }
    __syncthreads();

    const float l0 = fmaxf(SM_LF[0], 1e-30f);
    const float l1 = fmaxf(SM_LF[1], 1e-30f);
    const float l2 = fmaxf(SM_LF[2], 1e-30f);
    const float l3 = fmaxf(SM_LF[3], 1e-30f);
    g_po[(pbase + 0) * DD + tid] = __float2half(acc0 / l0);
    g_po[(pbase + 1) * DD + tid] = __float2half(acc1 / l1);
    g_po[(pbase + 2) * DD + tid] = __float2half(acc2 / l2);
    g_po[(pbase + 3) * DD + tid] = __float2half(acc3 / l3);
    if (tid < GG)
        g_plse[lbase + tid * RS] =
            SM_MF[tid] + __logf(fmaxf(SM_LF[tid], 1e-30f));
}

#define CTHREADS 256
#define NSLICE 8
#define PER_SLICE (RS / NSLICE)   // 16

__global__ void __launch_bounds__(CTHREADS)
combine_kernel(float* __restrict__ out)
{
    const int bh  = blockIdx.x;     // b*HQ + hq
    const int dq  = blockIdx.y;     // dim quarter 0..3
    const int tid = threadIdx.x;
    const int dl  = tid & 31;       // lane = dim within quarter
    const int sl  = tid >> 5;       // slice-warp 0..7
    const int d   = dq * 32 + dl;

    __shared__ float lse_s[RS];
    __shared__ float accs[NSLICE][32];
    __shared__ float wss[NSLICE];

    if (tid < RS)
        lse_s[tid] = g_plse[bh * RS + tid];   // one coalesced 512B row
    __syncthreads();

    // Global max via warp reduce (4 LDS + 5 SHFL; warp-uniform result).
    float gm;
    {
        float x = fmaxf(fmaxf(lse_s[dl], lse_s[dl + 32]),
                        fmaxf(lse_s[dl + 64], lse_s[dl + 96]));
        #pragma unroll
        for (int off = 16; off; off >>= 1)
            x = fmaxf(x, __shfl_xor_sync(0xffffffffu, x, off));
        gm = x;
    }

    // Each slice-warp accumulates its 16 partials for its 32 dims;
    // fully unrolled so the predicated LDGs front-batch (MLP up to 16).
    float acc = 0.f, ws = 0.f;
    #pragma unroll
    for (int t = 0; t < PER_SLICE; ++t) {
        const int   i   = sl * PER_SLICE + t;
        const float lse = lse_s[i];
        if (lse > -5.0e29f) {
            const float w = __expf(lse - gm);
            ws  += w;
            acc += w * __half2float(g_po[(i * (BB * HQ) + bh) * DD + d]);
        }
    }
    accs[sl][dl] = acc;
    if (dl == 0) wss[sl] = ws;
    __syncthreads();

    if (sl == 0) {
        float a = 0.f, wt = 0.f;
        #pragma unroll
        for (int k = 0; k < NSLICE; ++k) {
            a  += accs[k][dl];
            wt += wss[k];
        }
        out[bh * DD + d] = a / fmaxf(wt, 1e-30f);
    }
}

extern "C" void kernel_launch(void* const* d_in, const int* in_sizes, int n_in,
                              void* d_out, int out_size)
{
    (void)in_sizes; (void)n_in; (void)out_size;
    const float* q    = (const float*)d_in[0];
    const float* kc   = (const float*)d_in[1];
    const float* vc   = (const float*)d_in[2];
    const int*   lens = (const int*)d_in[3];
    const int*   bt   = (const int*)d_in[4];

    cudaFuncSetAttribute(decode_kernel,
                         cudaFuncAttributeMaxDynamicSharedMemorySize, SMEM_BYTES);

    dim3 grid1(NSPLIT, HKV, RR * BB);
    decode_kernel<<<grid1, 128, SMEM_BYTES>>>(q, kc, vc, lens, bt);
    dim3 grid2(BB * HQ, 4);
    combine_kernel<<<grid2, CTHREADS>>>((float*)d_out);
}